// round 1
// baseline (speedup 1.0000x reference)
#include <cuda_runtime.h>
#include <math.h>

#define HDIM 128
#define NN   299593
#define LEAF_S 37449

// scratch for hidden states (device global: no allocations allowed)
static __device__ float g_h[(size_t)NN * HDIM];

// ---------------------------------------------------------------------------
// Leaf kernel: h[i] = tanh((emb[x[i]*m[i]] @ W_in + b_in) * m[i])  for leaves
// Tile: 128 rows x 128 cols, 256 threads, 8x8 per thread, W_in in smem.
// ---------------------------------------------------------------------------
__global__ void __launch_bounds__(256, 2)
k_leaf(const int* __restrict__ x, const int* __restrict__ mask,
       const float* __restrict__ emb, const float* __restrict__ W_in,
       const float* __restrict__ b_in)
{
    extern __shared__ float sm[];
    float* Ws = sm;                                    // [128][128]
    float (*As)[136] = (float (*)[136])(sm + 128 * 128); // [16][136] k-major A chunk

    const int tid  = threadIdx.x;
    const int row0 = LEAF_S + blockIdx.x * 128;

    for (int i = tid; i < 128 * 128 / 4; i += 256)
        ((float4*)Ws)[i] = ((const float4*)W_in)[i];

    const int tx = tid & 15, ty = tid >> 4;

    // each thread loads 2 float4 of the A chunk per k-step of 16
    const int r0 = tid >> 2,         kq0 = tid & 3;
    const int r1 = (tid + 256) >> 2, kq1 = (tid + 256) & 3;
    const int n0 = row0 + r0, n1 = row0 + r1;
    const float m0 = (float)mask[n0], m1 = (float)mask[n1];
    const float* src0 = emb + (size_t)(x[n0] * mask[n0]) * HDIM;
    const float* src1 = emb + (size_t)(x[n1] * mask[n1]) * HDIM;

    float acc[8][8];
#pragma unroll
    for (int i = 0; i < 8; i++)
#pragma unroll
        for (int j = 0; j < 8; j++) acc[i][j] = 0.f;

    for (int kk = 0; kk < 128; kk += 16) {
        __syncthreads();
        float4 v0 = *(const float4*)(src0 + kk + kq0 * 4);
        float4 v1 = *(const float4*)(src1 + kk + kq1 * 4);
        As[kq0 * 4 + 0][r0] = v0.x * m0; As[kq0 * 4 + 1][r0] = v0.y * m0;
        As[kq0 * 4 + 2][r0] = v0.z * m0; As[kq0 * 4 + 3][r0] = v0.w * m0;
        As[kq1 * 4 + 0][r1] = v1.x * m1; As[kq1 * 4 + 1][r1] = v1.y * m1;
        As[kq1 * 4 + 2][r1] = v1.z * m1; As[kq1 * 4 + 3][r1] = v1.w * m1;
        __syncthreads();
#pragma unroll
        for (int k = 0; k < 16; k++) {
            float a[8], b[8];
            *(float4*)(a)     = *(float4*)&As[k][ty * 8];
            *(float4*)(a + 4) = *(float4*)&As[k][ty * 8 + 4];
            *(float4*)(b)     = *(float4*)&Ws[(kk + k) * 128 + tx * 8];
            *(float4*)(b + 4) = *(float4*)&Ws[(kk + k) * 128 + tx * 8 + 4];
#pragma unroll
            for (int i = 0; i < 8; i++)
#pragma unroll
                for (int j = 0; j < 8; j++)
                    acc[i][j] = fmaf(a[i], b[j], acc[i][j]);
        }
    }

    float bv[8];
    *(float4*)(bv)     = *(const float4*)(b_in + tx * 8);
    *(float4*)(bv + 4) = *(const float4*)(b_in + tx * 8 + 4);

#pragma unroll
    for (int i = 0; i < 8; i++) {
        const int node = row0 + ty * 8 + i;
        const float mf = (float)mask[node];
        float o[8];
#pragma unroll
        for (int j = 0; j < 8; j++) o[j] = tanhf(acc[i][j] + bv[j] * mf);
        float* dst = g_h + (size_t)node * HDIM + tx * 8;
        *(float4*)(dst)     = *(float4*)(o);
        *(float4*)(dst + 4) = *(float4*)(o + 4);
    }
}

// ---------------------------------------------------------------------------
// Internal-level kernel: h[i] = tanh((emb@W_in+b)*m + (sum_c h[child_c]) @ U)
// Fused as one K=256 GEMM: A' = [m*emb_row | child_sum], W' = [W_in ; U].
// CT = columns computed per block (128 for big levels, 32 to cut small-level
// latency). 256 threads.
// ---------------------------------------------------------------------------
template <int CT>
__global__ void __launch_bounds__(256, 1)
k_level(int s, int n,
        const int* __restrict__ x, const int* __restrict__ mask,
        const int* __restrict__ children,
        const float* __restrict__ emb,
        const float* __restrict__ W_in, const float* __restrict__ b_in,
        const float* __restrict__ U)
{
    extern __shared__ float sm[];
    float* Ws = sm;                                      // [256][128]
    float (*As)[136] = (float (*)[136])(sm + 256 * 128); // [16][136]

    const int tid  = threadIdx.x;
    const int row0 = blockIdx.x * 128;   // local row within level
    const int col0 = blockIdx.y * CT;
    const int e    = s + n;

    for (int i = tid; i < 128 * 128 / 4; i += 256) {
        ((float4*)Ws)[i]                 = ((const float4*)W_in)[i];
        ((float4*)Ws)[i + 128 * 128 / 4] = ((const float4*)U)[i];
    }

    constexpr int TX = CT / 8;   // threads along columns
    constexpr int TM = CT / 16;  // rows per thread  (so TX * (256/TX) * TM covers 128 rows)
    const int tx = tid % TX, ty = tid / TX;

    const int r0 = tid >> 2,         kq0 = tid & 3;
    const int r1 = (tid + 256) >> 2, kq1 = (tid + 256) & 3;
    const int nd0 = s + row0 + r0;
    const int nd1 = s + row0 + r1;
    const int nd0c = (nd0 < e) ? nd0 : s;
    const int nd1c = (nd1 < e) ? nd1 : s;
    const float m0 = (nd0 < e) ? (float)mask[nd0c] : 0.f;
    const float m1 = (nd1 < e) ? (float)mask[nd1c] : 0.f;
    const float* src0 = emb + (size_t)(x[nd0c] * mask[nd0c]) * HDIM;
    const float* src1 = emb + (size_t)(x[nd1c] * mask[nd1c]) * HDIM;

    int cidx0[8], cidx1[8];
#pragma unroll
    for (int c = 0; c < 8; c++) {
        cidx0[c] = children[(size_t)nd0c * 8 + c];
        cidx1[c] = children[(size_t)nd1c * 8 + c];
    }

    float acc[TM][8];
#pragma unroll
    for (int i = 0; i < TM; i++)
#pragma unroll
        for (int j = 0; j < 8; j++) acc[i][j] = 0.f;

    // ---- Phase A: (m * emb_row) @ W_in ----
    for (int kk = 0; kk < 128; kk += 16) {
        __syncthreads();
        float4 v0 = *(const float4*)(src0 + kk + kq0 * 4);
        float4 v1 = *(const float4*)(src1 + kk + kq1 * 4);
        As[kq0 * 4 + 0][r0] = v0.x * m0; As[kq0 * 4 + 1][r0] = v0.y * m0;
        As[kq0 * 4 + 2][r0] = v0.z * m0; As[kq0 * 4 + 3][r0] = v0.w * m0;
        As[kq1 * 4 + 0][r1] = v1.x * m1; As[kq1 * 4 + 1][r1] = v1.y * m1;
        As[kq1 * 4 + 2][r1] = v1.z * m1; As[kq1 * 4 + 3][r1] = v1.w * m1;
        __syncthreads();
#pragma unroll
        for (int k = 0; k < 16; k++) {
            float b[8];
            *(float4*)(b)     = *(float4*)&Ws[(kk + k) * 128 + col0 + tx * 8];
            *(float4*)(b + 4) = *(float4*)&Ws[(kk + k) * 128 + col0 + tx * 8 + 4];
            float a[TM];
#pragma unroll
            for (int i = 0; i < TM; i++) a[i] = As[k][ty * TM + i];
#pragma unroll
            for (int i = 0; i < TM; i++)
#pragma unroll
                for (int j = 0; j < 8; j++)
                    acc[i][j] = fmaf(a[i], b[j], acc[i][j]);
        }
    }

    // ---- Phase B: (sum of 8 children h rows) @ U ----
    for (int kk = 0; kk < 128; kk += 16) {
        __syncthreads();
        float4 c0 = make_float4(0.f, 0.f, 0.f, 0.f);
        float4 c1 = make_float4(0.f, 0.f, 0.f, 0.f);
#pragma unroll
        for (int c = 0; c < 8; c++) {
            float4 v0 = *(const float4*)(g_h + (size_t)cidx0[c] * HDIM + kk + kq0 * 4);
            float4 v1 = *(const float4*)(g_h + (size_t)cidx1[c] * HDIM + kk + kq1 * 4);
            c0.x += v0.x; c0.y += v0.y; c0.z += v0.z; c0.w += v0.w;
            c1.x += v1.x; c1.y += v1.y; c1.z += v1.z; c1.w += v1.w;
        }
        As[kq0 * 4 + 0][r0] = c0.x; As[kq0 * 4 + 1][r0] = c0.y;
        As[kq0 * 4 + 2][r0] = c0.z; As[kq0 * 4 + 3][r0] = c0.w;
        As[kq1 * 4 + 0][r1] = c1.x; As[kq1 * 4 + 1][r1] = c1.y;
        As[kq1 * 4 + 2][r1] = c1.z; As[kq1 * 4 + 3][r1] = c1.w;
        __syncthreads();
#pragma unroll
        for (int k = 0; k < 16; k++) {
            float b[8];
            *(float4*)(b)     = *(float4*)&Ws[(128 + kk + k) * 128 + col0 + tx * 8];
            *(float4*)(b + 4) = *(float4*)&Ws[(128 + kk + k) * 128 + col0 + tx * 8 + 4];
            float a[TM];
#pragma unroll
            for (int i = 0; i < TM; i++) a[i] = As[k][ty * TM + i];
#pragma unroll
            for (int i = 0; i < TM; i++)
#pragma unroll
                for (int j = 0; j < 8; j++)
                    acc[i][j] = fmaf(a[i], b[j], acc[i][j]);
        }
    }

    float bv[8];
#pragma unroll
    for (int j = 0; j < 8; j++) bv[j] = b_in[col0 + tx * 8 + j];

#pragma unroll
    for (int i = 0; i < TM; i++) {
        const int node = s + row0 + ty * TM + i;
        if (node < e) {
            const float mf = (float)mask[node];
            float o[8];
#pragma unroll
            for (int j = 0; j < 8; j++) o[j] = tanhf(acc[i][j] + bv[j] * mf);
            float* dst = g_h + (size_t)node * HDIM + col0 + tx * 8;
            *(float4*)(dst)     = *(float4*)(o);
            *(float4*)(dst + 4) = *(float4*)(o + 4);
        }
    }
}

// ---------------------------------------------------------------------------
// Output kernel: out = g_h @ W_out + b_out   (all N rows)
// ---------------------------------------------------------------------------
__global__ void __launch_bounds__(256, 2)
k_out(const float* __restrict__ W_out, const float* __restrict__ b_out,
      float* __restrict__ out)
{
    extern __shared__ float sm[];
    float* Ws = sm;
    float (*As)[136] = (float (*)[136])(sm + 128 * 128);

    const int tid  = threadIdx.x;
    const int row0 = blockIdx.x * 128;

    for (int i = tid; i < 128 * 128 / 4; i += 256)
        ((float4*)Ws)[i] = ((const float4*)W_out)[i];

    const int tx = tid & 15, ty = tid >> 4;

    const int r0 = tid >> 2,         kq0 = tid & 3;
    const int r1 = (tid + 256) >> 2, kq1 = (tid + 256) & 3;
    int n0 = row0 + r0; if (n0 >= NN) n0 = NN - 1;
    int n1 = row0 + r1; if (n1 >= NN) n1 = NN - 1;
    const float* src0 = g_h + (size_t)n0 * HDIM;
    const float* src1 = g_h + (size_t)n1 * HDIM;

    float acc[8][8];
#pragma unroll
    for (int i = 0; i < 8; i++)
#pragma unroll
        for (int j = 0; j < 8; j++) acc[i][j] = 0.f;

    for (int kk = 0; kk < 128; kk += 16) {
        __syncthreads();
        float4 v0 = *(const float4*)(src0 + kk + kq0 * 4);
        float4 v1 = *(const float4*)(src1 + kk + kq1 * 4);
        As[kq0 * 4 + 0][r0] = v0.x; As[kq0 * 4 + 1][r0] = v0.y;
        As[kq0 * 4 + 2][r0] = v0.z; As[kq0 * 4 + 3][r0] = v0.w;
        As[kq1 * 4 + 0][r1] = v1.x; As[kq1 * 4 + 1][r1] = v1.y;
        As[kq1 * 4 + 2][r1] = v1.z; As[kq1 * 4 + 3][r1] = v1.w;
        __syncthreads();
#pragma unroll
        for (int k = 0; k < 16; k++) {
            float a[8], b[8];
            *(float4*)(a)     = *(float4*)&As[k][ty * 8];
            *(float4*)(a + 4) = *(float4*)&As[k][ty * 8 + 4];
            *(float4*)(b)     = *(float4*)&Ws[(kk + k) * 128 + tx * 8];
            *(float4*)(b + 4) = *(float4*)&Ws[(kk + k) * 128 + tx * 8 + 4];
#pragma unroll
            for (int i = 0; i < 8; i++)
#pragma unroll
                for (int j = 0; j < 8; j++)
                    acc[i][j] = fmaf(a[i], b[j], acc[i][j]);
        }
    }

    float bv[8];
    *(float4*)(bv)     = *(const float4*)(b_out + tx * 8);
    *(float4*)(bv + 4) = *(const float4*)(b_out + tx * 8 + 4);

#pragma unroll
    for (int i = 0; i < 8; i++) {
        const int node = row0 + ty * 8 + i;
        if (node < NN) {
            float o[8];
#pragma unroll
            for (int j = 0; j < 8; j++) o[j] = acc[i][j] + bv[j];
            float* dst = out + (size_t)node * HDIM + tx * 8;
            *(float4*)(dst)     = *(float4*)(o);
            *(float4*)(dst + 4) = *(float4*)(o + 4);
        }
    }
}

// ---------------------------------------------------------------------------
extern "C" void kernel_launch(void* const* d_in, const int* in_sizes, int n_in,
                              void* d_out, int out_size)
{
    const int*   x        = (const int*)  d_in[0];
    const int*   mask     = (const int*)  d_in[1];
    const int*   children = (const int*)  d_in[2];
    const float* emb      = (const float*)d_in[3];
    const float* W_in     = (const float*)d_in[4];
    const float* b_in     = (const float*)d_in[5];
    const float* U        = (const float*)d_in[6];
    const float* W_out    = (const float*)d_in[7];
    const float* b_out    = (const float*)d_in[8];
    float*       out      = (float*)d_out;
    (void)in_sizes; (void)n_in; (void)out_size;

    const size_t sm_gemm  = (size_t)(128 * 128 + 16 * 136) * sizeof(float); //  74 KB
    const size_t sm_level = (size_t)(256 * 128 + 16 * 136) * sizeof(float); // 137 KB

    cudaFuncSetAttribute(k_leaf,      cudaFuncAttributeMaxDynamicSharedMemorySize, (int)sm_gemm);
    cudaFuncSetAttribute(k_out,       cudaFuncAttributeMaxDynamicSharedMemorySize, (int)sm_gemm);
    cudaFuncSetAttribute(k_level<128>,cudaFuncAttributeMaxDynamicSharedMemorySize, (int)sm_level);
    cudaFuncSetAttribute(k_level<32>, cudaFuncAttributeMaxDynamicSharedMemorySize, (int)sm_level);

    // Level 6 (leaves): 262144 nodes = 2048 tiles exactly
    k_leaf<<<2048, 256, sm_gemm>>>(x, mask, emb, W_in, b_in);

    static const int offs[8] = {0, 1, 9, 73, 585, 4681, 37449, 299593};
    for (int l = 5; l >= 0; --l) {
        const int s = offs[l];
        const int n = offs[l + 1] - offs[l];
        const int gx = (n + 127) / 128;
        if (n >= 8192) {
            dim3 grid(gx, 1);
            k_level<128><<<grid, 256, sm_level>>>(s, n, x, mask, children, emb, W_in, b_in, U);
        } else {
            dim3 grid(gx, 4);  // split columns to cut dependent-chain latency
            k_level<32><<<grid, 256, sm_level>>>(s, n, x, mask, children, emb, W_in, b_in, U);
        }
    }

    k_out<<<(NN + 127) / 128, 256, sm_gemm>>>(W_out, b_out, out);
}

// round 2
// speedup vs baseline: 2.7765x; 2.7765x over previous
#include <cuda_runtime.h>
#include <math.h>

#define HDIM    128
#define NN      299593
#define NINT    37449     // internal nodes (levels 0..5)
#define NVOC    32000

// device scratch (no allocations allowed)
static __device__ float g_Pb[(size_t)NVOC * HDIM];  // emb @ W_in + b_in
static __device__ float g_T [(size_t)NVOC * HDIM];  // tanh(g_Pb)
static __device__ float g_Q [(size_t)NVOC * HDIM];  // g_T @ W_out
static __device__ float g_h [(size_t)NINT * HDIM];  // hidden states, internal nodes

// ---------------------------------------------------------------------------
// Vocab GEMM: O = A @ W (+bias); optionally also write tanh(O) to O2.
// A contiguous [32000 x 128], W [128 x 128] in smem, 128x128 tile, 8x8/thread.
// ---------------------------------------------------------------------------
template <bool BT>
__global__ void __launch_bounds__(256, 2)
k_vgemm(const float* __restrict__ A, const float* __restrict__ W,
        const float* __restrict__ bias, float* __restrict__ O1,
        float* __restrict__ O2)
{
    extern __shared__ float sm[];
    float* Ws = sm;                                      // [128][128]
    float (*As)[136] = (float (*)[136])(sm + 128 * 128); // [16][136]

    const int tid  = threadIdx.x;
    const int row0 = blockIdx.x * 128;

    for (int i = tid; i < 128 * 128 / 4; i += 256)
        ((float4*)Ws)[i] = ((const float4*)W)[i];

    const int tx = tid & 15, ty = tid >> 4;
    const int r0 = tid >> 2, kq = tid & 3;
    const int r1 = r0 + 64;
    const float* src0 = A + (size_t)(row0 + r0) * HDIM;
    const float* src1 = A + (size_t)(row0 + r1) * HDIM;

    float acc[8][8];
#pragma unroll
    for (int i = 0; i < 8; i++)
#pragma unroll
        for (int j = 0; j < 8; j++) acc[i][j] = 0.f;

    for (int kk = 0; kk < 128; kk += 16) {
        __syncthreads();
        float4 v0 = *(const float4*)(src0 + kk + kq * 4);
        float4 v1 = *(const float4*)(src1 + kk + kq * 4);
        As[kq * 4 + 0][r0] = v0.x; As[kq * 4 + 1][r0] = v0.y;
        As[kq * 4 + 2][r0] = v0.z; As[kq * 4 + 3][r0] = v0.w;
        As[kq * 4 + 0][r1] = v1.x; As[kq * 4 + 1][r1] = v1.y;
        As[kq * 4 + 2][r1] = v1.z; As[kq * 4 + 3][r1] = v1.w;
        __syncthreads();
#pragma unroll
        for (int k = 0; k < 16; k++) {
            float a[8], b[8];
            *(float4*)(a)     = *(float4*)&As[k][ty * 8];
            *(float4*)(a + 4) = *(float4*)&As[k][ty * 8 + 4];
            *(float4*)(b)     = *(float4*)&Ws[(kk + k) * 128 + tx * 8];
            *(float4*)(b + 4) = *(float4*)&Ws[(kk + k) * 128 + tx * 8 + 4];
#pragma unroll
            for (int i = 0; i < 8; i++)
#pragma unroll
                for (int j = 0; j < 8; j++)
                    acc[i][j] = fmaf(a[i], b[j], acc[i][j]);
        }
    }

    float bv[8];
    if (BT) {
        *(float4*)(bv)     = *(const float4*)(bias + tx * 8);
        *(float4*)(bv + 4) = *(const float4*)(bias + tx * 8 + 4);
    }

#pragma unroll
    for (int i = 0; i < 8; i++) {
        const size_t row = row0 + ty * 8 + i;
        float o[8];
#pragma unroll
        for (int j = 0; j < 8; j++) o[j] = BT ? (acc[i][j] + bv[j]) : acc[i][j];
        float* d1 = O1 + row * HDIM + tx * 8;
        *(float4*)(d1)     = *(float4*)(o);
        *(float4*)(d1 + 4) = *(float4*)(o + 4);
        if (BT) {
            float t[8];
#pragma unroll
            for (int j = 0; j < 8; j++) t[j] = tanhf(o[j]);
            float* d2 = O2 + row * HDIM + tx * 8;
            *(float4*)(d2)     = *(float4*)(t);
            *(float4*)(d2 + 4) = *(float4*)(t + 4);
        }
    }
}

// ---------------------------------------------------------------------------
// Level kernel: h[node] = tanh(Pb[x]*m + (sum_c child_h) @ U)
// LEAF=true: children are leaves -> child_h = mask_c * T[x_c]; else g_h[child].
// CT columns per block. 256 threads.
// ---------------------------------------------------------------------------
template <int CT, bool LEAF>
__global__ void __launch_bounds__(256, 2)
k_level2(int s, int n,
         const int* __restrict__ x, const int* __restrict__ mask,
         const int* __restrict__ children,
         const float* __restrict__ U)
{
    extern __shared__ float sm[];
    float* Us = sm;                                      // [128][128]
    float (*As)[136] = (float (*)[136])(sm + 128 * 128);

    const int tid  = threadIdx.x;
    const int row0 = blockIdx.x * 128;
    const int col0 = blockIdx.y * CT;
    const int e    = s + n;

    for (int i = tid; i < 128 * 128 / 4; i += 256)
        ((float4*)Us)[i] = ((const float4*)U)[i];

    constexpr int TX = CT / 8;
    constexpr int TM = CT / 16;
    const int tx = tid % TX, ty = tid / TX;

    const int r0 = tid >> 2, kq = tid & 3;
    const int r1 = r0 + 64;

    const float* ptr0[8]; const float* ptr1[8];
    float f0[8], f1[8];
    {
        const int nd0 = s + row0 + r0;
        const int nd1 = s + row0 + r1;
        const bool v0 = nd0 < e, v1 = nd1 < e;
        const int b0 = v0 ? nd0 : s, b1 = v1 ? nd1 : s;
#pragma unroll
        for (int c = 0; c < 8; c++) {
            const int ch0 = children[(size_t)b0 * 8 + c];
            const int ch1 = children[(size_t)b1 * 8 + c];
            if (LEAF) {
                const int m0 = mask[ch0], m1 = mask[ch1];
                ptr0[c] = g_T + (size_t)(x[ch0] * m0) * HDIM;
                ptr1[c] = g_T + (size_t)(x[ch1] * m1) * HDIM;
                f0[c] = v0 ? (float)m0 : 0.f;
                f1[c] = v1 ? (float)m1 : 0.f;
            } else {
                ptr0[c] = g_h + (size_t)ch0 * HDIM;
                ptr1[c] = g_h + (size_t)ch1 * HDIM;
                f0[c] = v0 ? 1.f : 0.f;
                f1[c] = v1 ? 1.f : 0.f;
            }
        }
    }

    float acc[TM][8];
#pragma unroll
    for (int i = 0; i < TM; i++)
#pragma unroll
        for (int j = 0; j < 8; j++) acc[i][j] = 0.f;

    for (int kk = 0; kk < 128; kk += 16) {
        __syncthreads();
        float4 c0 = make_float4(0.f, 0.f, 0.f, 0.f);
        float4 c1 = make_float4(0.f, 0.f, 0.f, 0.f);
#pragma unroll
        for (int c = 0; c < 8; c++) {
            float4 u0 = *(const float4*)(ptr0[c] + kk + kq * 4);
            float4 u1 = *(const float4*)(ptr1[c] + kk + kq * 4);
            c0.x = fmaf(u0.x, f0[c], c0.x); c0.y = fmaf(u0.y, f0[c], c0.y);
            c0.z = fmaf(u0.z, f0[c], c0.z); c0.w = fmaf(u0.w, f0[c], c0.w);
            c1.x = fmaf(u1.x, f1[c], c1.x); c1.y = fmaf(u1.y, f1[c], c1.y);
            c1.z = fmaf(u1.z, f1[c], c1.z); c1.w = fmaf(u1.w, f1[c], c1.w);
        }
        As[kq * 4 + 0][r0] = c0.x; As[kq * 4 + 1][r0] = c0.y;
        As[kq * 4 + 2][r0] = c0.z; As[kq * 4 + 3][r0] = c0.w;
        As[kq * 4 + 0][r1] = c1.x; As[kq * 4 + 1][r1] = c1.y;
        As[kq * 4 + 2][r1] = c1.z; As[kq * 4 + 3][r1] = c1.w;
        __syncthreads();
#pragma unroll
        for (int k = 0; k < 16; k++) {
            float b[8];
            *(float4*)(b)     = *(float4*)&Us[(kk + k) * 128 + col0 + tx * 8];
            *(float4*)(b + 4) = *(float4*)&Us[(kk + k) * 128 + col0 + tx * 8 + 4];
            float a[TM];
#pragma unroll
            for (int i = 0; i < TM; i++) a[i] = As[k][ty * TM + i];
#pragma unroll
            for (int i = 0; i < TM; i++)
#pragma unroll
                for (int j = 0; j < 8; j++)
                    acc[i][j] = fmaf(a[i], b[j], acc[i][j]);
        }
    }

#pragma unroll
    for (int i = 0; i < TM; i++) {
        const int node = s + row0 + ty * TM + i;
        if (node < e) {
            const float mf = (float)mask[node];
            const int   xm = x[node] * mask[node];
            const float* hb = g_Pb + (size_t)xm * HDIM + col0 + tx * 8;
            float o[8];
#pragma unroll
            for (int j = 0; j < 8; j++)
                o[j] = tanhf(acc[i][j] + hb[j] * mf);
            float* dst = g_h + (size_t)node * HDIM + col0 + tx * 8;
            *(float4*)(dst)     = *(float4*)(o);
            *(float4*)(dst + 4) = *(float4*)(o + 4);
        }
    }
}

// ---------------------------------------------------------------------------
// Per-node kernel for tiny levels (<=512 nodes). One block per node.
// h[node] = tanh(Pb[x]*m + (sum_c g_h[child]) @ U), 128 threads = 128 cols.
// ---------------------------------------------------------------------------
__global__ void __launch_bounds__(128, 8)
k_node(int s, const int* __restrict__ x, const int* __restrict__ mask,
       const int* __restrict__ children, const float* __restrict__ U)
{
    __shared__ float agg[128];
    const int node = s + blockIdx.x;
    const int t = threadIdx.x;

    float sum = 0.f;
#pragma unroll
    for (int c = 0; c < 8; c++)
        sum += g_h[(size_t)children[(size_t)node * 8 + c] * HDIM + t];
    agg[t] = sum;
    __syncthreads();

    float a0 = 0.f, a1 = 0.f, a2 = 0.f, a3 = 0.f;
#pragma unroll 8
    for (int k = 0; k < 128; k += 4) {
        a0 = fmaf(agg[k + 0], U[(k + 0) * 128 + t], a0);
        a1 = fmaf(agg[k + 1], U[(k + 1) * 128 + t], a1);
        a2 = fmaf(agg[k + 2], U[(k + 2) * 128 + t], a2);
        a3 = fmaf(agg[k + 3], U[(k + 3) * 128 + t], a3);
    }

    const float mf = (float)mask[node];
    const int   xm = x[node] * mask[node];
    const float hin = g_Pb[(size_t)xm * HDIM + t] * mf;
    g_h[(size_t)node * HDIM + t] = tanhf(hin + (a0 + a1) + (a2 + a3));
}

// ---------------------------------------------------------------------------
// Output GEMM for internal nodes: out[0..NINT) = g_h @ W_out + b_out
// ---------------------------------------------------------------------------
__global__ void __launch_bounds__(256, 2)
k_out_int(const float* __restrict__ W_out, const float* __restrict__ b_out,
          float* __restrict__ out)
{
    extern __shared__ float sm[];
    float* Ws = sm;
    float (*As)[136] = (float (*)[136])(sm + 128 * 128);

    const int tid  = threadIdx.x;
    const int row0 = blockIdx.x * 128;

    for (int i = tid; i < 128 * 128 / 4; i += 256)
        ((float4*)Ws)[i] = ((const float4*)W_out)[i];

    const int tx = tid & 15, ty = tid >> 4;
    const int r0 = tid >> 2, kq = tid & 3;
    const int r1 = r0 + 64;
    int n0 = row0 + r0; if (n0 >= NINT) n0 = NINT - 1;
    int n1 = row0 + r1; if (n1 >= NINT) n1 = NINT - 1;
    const float* src0 = g_h + (size_t)n0 * HDIM;
    const float* src1 = g_h + (size_t)n1 * HDIM;

    float acc[8][8];
#pragma unroll
    for (int i = 0; i < 8; i++)
#pragma unroll
        for (int j = 0; j < 8; j++) acc[i][j] = 0.f;

    for (int kk = 0; kk < 128; kk += 16) {
        __syncthreads();
        float4 v0 = *(const float4*)(src0 + kk + kq * 4);
        float4 v1 = *(const float4*)(src1 + kk + kq * 4);
        As[kq * 4 + 0][r0] = v0.x; As[kq * 4 + 1][r0] = v0.y;
        As[kq * 4 + 2][r0] = v0.z; As[kq * 4 + 3][r0] = v0.w;
        As[kq * 4 + 0][r1] = v1.x; As[kq * 4 + 1][r1] = v1.y;
        As[kq * 4 + 2][r1] = v1.z; As[kq * 4 + 3][r1] = v1.w;
        __syncthreads();
#pragma unroll
        for (int k = 0; k < 16; k++) {
            float a[8], b[8];
            *(float4*)(a)     = *(float4*)&As[k][ty * 8];
            *(float4*)(a + 4) = *(float4*)&As[k][ty * 8 + 4];
            *(float4*)(b)     = *(float4*)&Ws[(kk + k) * 128 + tx * 8];
            *(float4*)(b + 4) = *(float4*)&Ws[(kk + k) * 128 + tx * 8 + 4];
#pragma unroll
            for (int i = 0; i < 8; i++)
#pragma unroll
                for (int j = 0; j < 8; j++)
                    acc[i][j] = fmaf(a[i], b[j], acc[i][j]);
        }
    }

    float bv[8];
    *(float4*)(bv)     = *(const float4*)(b_out + tx * 8);
    *(float4*)(bv + 4) = *(const float4*)(b_out + tx * 8 + 4);

#pragma unroll
    for (int i = 0; i < 8; i++) {
        const int node = row0 + ty * 8 + i;
        if (node < NINT) {
            float o[8];
#pragma unroll
            for (int j = 0; j < 8; j++) o[j] = acc[i][j] + bv[j];
            float* dst = out + (size_t)node * HDIM + tx * 8;
            *(float4*)(dst)     = *(float4*)(o);
            *(float4*)(dst + 4) = *(float4*)(o + 4);
        }
    }
}

// ---------------------------------------------------------------------------
// Leaf output gather: out[leaf] = mask ? Q[x] + b_out : b_out
// One float4 per thread.
// ---------------------------------------------------------------------------
__global__ void __launch_bounds__(256)
k_out_leaf(const int* __restrict__ x, const int* __restrict__ mask,
           const float* __restrict__ b_out, float* __restrict__ out)
{
    const int idx = blockIdx.x * 256 + threadIdx.x;
    const int r = idx >> 5;        // leaf index 0..262143
    const int c = idx & 31;        // float4 column
    const int node = NINT + r;
    const int m  = mask[node];
    const int xm = x[node] * m;
    const float mf = (float)m;
    float4 q = ((const float4*)g_Q)[(size_t)xm * 32 + c];
    float4 b = ((const float4*)b_out)[c];
    float4 o = make_float4(fmaf(q.x, mf, b.x), fmaf(q.y, mf, b.y),
                           fmaf(q.z, mf, b.z), fmaf(q.w, mf, b.w));
    ((float4*)out)[(size_t)node * 32 + c] = o;
}

// ---------------------------------------------------------------------------
extern "C" void kernel_launch(void* const* d_in, const int* in_sizes, int n_in,
                              void* d_out, int out_size)
{
    const int*   x        = (const int*)  d_in[0];
    const int*   mask     = (const int*)  d_in[1];
    const int*   children = (const int*)  d_in[2];
    const float* emb      = (const float*)d_in[3];
    const float* W_in     = (const float*)d_in[4];
    const float* b_in     = (const float*)d_in[5];
    const float* U        = (const float*)d_in[6];
    const float* W_out    = (const float*)d_in[7];
    const float* b_out    = (const float*)d_in[8];
    float*       out      = (float*)d_out;
    (void)in_sizes; (void)n_in; (void)out_size;

    const size_t sm = (size_t)(128 * 128 + 16 * 136) * sizeof(float); // 74 KB

    cudaFuncSetAttribute(k_vgemm<true>,     cudaFuncAttributeMaxDynamicSharedMemorySize, (int)sm);
    cudaFuncSetAttribute(k_vgemm<false>,    cudaFuncAttributeMaxDynamicSharedMemorySize, (int)sm);
    cudaFuncSetAttribute((const void*)k_level2<64, true>,  cudaFuncAttributeMaxDynamicSharedMemorySize, (int)sm);
    cudaFuncSetAttribute((const void*)k_level2<32, false>, cudaFuncAttributeMaxDynamicSharedMemorySize, (int)sm);
    cudaFuncSetAttribute(k_out_int,         cudaFuncAttributeMaxDynamicSharedMemorySize, (int)sm);

    float *Pb, *T, *Q;
    cudaGetSymbolAddress((void**)&Pb, g_Pb);
    cudaGetSymbolAddress((void**)&T,  g_T);
    cudaGetSymbolAddress((void**)&Q,  g_Q);

    // Stage 1: Pb = emb@W_in + b_in, T = tanh(Pb)   (32000 rows = 250 tiles)
    k_vgemm<true><<<250, 256, sm>>>(emb, W_in, b_in, Pb, T);
    // Stage 2: Q = T @ W_out
    k_vgemm<false><<<250, 256, sm>>>(T, W_out, nullptr, Q, nullptr);

    // Level 5: 32768 nodes, children are leaves (gather T)
    k_level2<64, true><<<dim3(256, 2), 256, sm>>>(4681, 32768, x, mask, children, U);
    // Level 4: 4096 nodes
    k_level2<32, false><<<dim3(32, 4), 256, sm>>>(585, 4096, x, mask, children, U);
    // Levels 3..0: per-node
    k_node<<<512, 128>>>(73, x, mask, children, U);
    k_node<<<64, 128>>>(9, x, mask, children, U);
    k_node<<<8, 128>>>(1, x, mask, children, U);
    k_node<<<1, 128>>>(0, x, mask, children, U);

    // Outputs
    k_out_int<<<(NINT + 127) / 128, 256, sm>>>(W_out, b_out, out);
    k_out_leaf<<<32768, 256>>>(x, mask, b_out, out);
}

// round 4
// speedup vs baseline: 2.8310x; 1.0196x over previous
#include <cuda_runtime.h>
#include <math.h>
#include <stdint.h>

#define NINT 37449
#define NVOC 32000

// ---------------- device scratch (no allocs allowed) ----------------
static __device__ float  g_Pb[(size_t)NVOC * 128]; // emb@W_in + b_in
static __device__ float  g_T [(size_t)NVOC * 128]; // tanh(Pb)
static __device__ float  g_Q [(size_t)NVOC * 128]; // T@W_out
static __device__ float  g_h [(size_t)NINT * 128]; // hidden, internal nodes
static __device__ float2 g_Bfrag[3][8192];         // {Win,U,Wout} mma-fragment images

// smem layout: As [128][132] floats, then Bf [8192] float2
#define AS_FLOATS (128 * 132)
#define AS_BYTES  (AS_FLOATS * 4)              // 67584
#define SMEM_BYTES (AS_BYTES + 8192 * 8)       // 133120

__device__ __forceinline__ void split(float v, uint32_t& hi, uint32_t& lo) {
    uint32_t u = __float_as_uint(v) & 0xffffe000u;
    hi = u;
    lo = __float_as_uint(v - __uint_as_float(u));
}

__device__ __forceinline__ void mma8(float d[4], const uint32_t a[4],
                                     uint32_t b0, uint32_t b1) {
    asm volatile(
        "mma.sync.aligned.m16n8k8.row.col.f32.tf32.tf32.f32 "
        "{%0,%1,%2,%3}, {%4,%5,%6,%7}, {%8,%9}, {%0,%1,%2,%3};"
        : "+f"(d[0]), "+f"(d[1]), "+f"(d[2]), "+f"(d[3])
        : "r"(a[0]), "r"(a[1]), "r"(a[2]), "r"(a[3]), "r"(b0), "r"(b1));
}

// 128x128x128 tile GEMM, tf32 x3. Warp (wr,wc) computes rows wr*32..+32,
// cols wc*64..+64. Accumulators acc[mt][nt][4].
__device__ __forceinline__ void gemm_core(const float* __restrict__ As,
                                          const float2* __restrict__ Bf,
                                          int wr, int wc, int lane,
                                          float acc[2][8][4])
{
    const int rA = wr * 32 + (lane >> 2);
    const int cA = lane & 3;
#pragma unroll 2
    for (int ks = 0; ks < 16; ks++) {
        uint32_t ahi[2][4], alo[2][4];
#pragma unroll
        for (int mt = 0; mt < 2; mt++) {
            const int r = rA + mt * 16;
            const int c = ks * 8 + cA;
            split(As[r * 132 + c],           ahi[mt][0], alo[mt][0]);
            split(As[(r + 8) * 132 + c],     ahi[mt][1], alo[mt][1]);
            split(As[r * 132 + c + 4],       ahi[mt][2], alo[mt][2]);
            split(As[(r + 8) * 132 + c + 4], ahi[mt][3], alo[mt][3]);
        }
#pragma unroll
        for (int nt = 0; nt < 8; nt++) {
            float2 b = Bf[(ks * 16 + wc * 8 + nt) * 32 + lane];
            uint32_t bh0, bl0, bh1, bl1;
            split(b.x, bh0, bl0);
            split(b.y, bh1, bl1);
#pragma unroll
            for (int mt = 0; mt < 2; mt++) {
                mma8(acc[mt][nt], ahi[mt], bh0, bh1);
                mma8(acc[mt][nt], ahi[mt], bl0, bl1);
                mma8(acc[mt][nt], alo[mt], bh0, bh1);
            }
        }
    }
}

__device__ __forceinline__ void load_Bf(float2* Bf, int w, int tid) {
    const float4* src = (const float4*)g_Bfrag[w];
    float4* dst = (float4*)Bf;
    for (int i = tid; i < 4096; i += 256) dst[i] = src[i];
}

// ---------------------------------------------------------------------------
// k_prep: build mma-fragment images of the 3 weights (B[n][k] = W[k][n]).
// frag index: [w][ks*512 + ntg*32 + lane] = {W[k0][n], W[k0+4][n]},
//   n = ntg*8 + lane/4, k0 = ks*8 + lane%4.
// ---------------------------------------------------------------------------
__global__ void k_prep(const float* __restrict__ Win, const float* __restrict__ U,
                       const float* __restrict__ Wout)
{
    int i = blockIdx.x * 256 + threadIdx.x;
    if (i < 3 * 8192) {
        int w = i >> 13, r = i & 8191;
        int ks = r >> 9, ntg = (r >> 5) & 15, lane = r & 31;
        int n = ntg * 8 + (lane >> 2);
        int k0 = ks * 8 + (lane & 3);
        const float* W = (w == 0) ? Win : ((w == 1) ? U : Wout);
        g_Bfrag[w][r] = make_float2(W[k0 * 128 + n], W[(k0 + 4) * 128 + n]);
    }
}

// ---------------------------------------------------------------------------
// k_vocab: per 128 vocab rows: Pb = emb@W_in + b_in; T = tanh(Pb); Q = T@W_out
// ---------------------------------------------------------------------------
__global__ void __launch_bounds__(256, 1)
k_vocab(const float* __restrict__ emb, const float* __restrict__ b_in)
{
    extern __shared__ char sm[];
    float*  As = (float*)sm;
    float2* Bf = (float2*)(sm + AS_BYTES);

    const int tid = threadIdx.x, wid = tid >> 5, lane = tid & 31;
    const int wr = wid & 3, wc = wid >> 2;
    const int row0 = blockIdx.x * 128;

    // stage emb rows
    for (int i = tid; i < 4096; i += 256) {
        int row = i >> 5, q = i & 31;
        float4 v = ((const float4*)emb)[(size_t)(row0 + row) * 32 + q];
        *(float4*)&As[row * 132 + q * 4] = v;
    }
    load_Bf(Bf, 0, tid); // W_in
    __syncthreads();

    float acc[2][8][4];
#pragma unroll
    for (int a = 0; a < 2; a++)
#pragma unroll
        for (int b = 0; b < 8; b++)
#pragma unroll
            for (int c = 0; c < 4; c++) acc[a][b][c] = 0.f;
    gemm_core(As, Bf, wr, wc, lane, acc);

    // epilogue 1: Pb, T; restage T into As (own rows only -> no sync needed)
#pragma unroll
    for (int mt = 0; mt < 2; mt++)
#pragma unroll
        for (int h = 0; h < 2; h++) {
            const int r = wr * 32 + mt * 16 + (lane >> 2) + h * 8;
            const size_t node = row0 + r;
#pragma unroll
            for (int nt = 0; nt < 8; nt++) {
                const int col = wc * 64 + nt * 8 + (lane & 3) * 2;
                float2 b = *(const float2*)&b_in[col];
                float p0 = acc[mt][nt][h * 2]     + b.x;
                float p1 = acc[mt][nt][h * 2 + 1] + b.y;
                *(float2*)&g_Pb[node * 128 + col] = make_float2(p0, p1);
                float t0 = tanhf(p0), t1 = tanhf(p1);
                *(float2*)&g_T[node * 128 + col] = make_float2(t0, t1);
                As[r * 132 + col]     = t0;
                As[r * 132 + col + 1] = t1;
            }
        }
    __syncthreads();           // all warps done with W_in frags + As writes
    load_Bf(Bf, 2, tid);       // W_out
    __syncthreads();

#pragma unroll
    for (int a = 0; a < 2; a++)
#pragma unroll
        for (int b = 0; b < 8; b++)
#pragma unroll
            for (int c = 0; c < 4; c++) acc[a][b][c] = 0.f;
    gemm_core(As, Bf, wr, wc, lane, acc);

#pragma unroll
    for (int mt = 0; mt < 2; mt++)
#pragma unroll
        for (int h = 0; h < 2; h++) {
            const size_t node = row0 + wr * 32 + mt * 16 + (lane >> 2) + h * 8;
#pragma unroll
            for (int nt = 0; nt < 8; nt++) {
                const int col = wc * 64 + nt * 8 + (lane & 3) * 2;
                *(float2*)&g_Q[node * 128 + col] =
                    make_float2(acc[mt][nt][h * 2], acc[mt][nt][h * 2 + 1]);
            }
        }
}

// ---------------------------------------------------------------------------
// k_level_t: h[node] = tanh(Pb[x*m]*m + (sum children) @ U)
// ---------------------------------------------------------------------------
template <bool LEAF>
__global__ void __launch_bounds__(256, 1)
k_level_t(int s, int n, const int* __restrict__ x, const int* __restrict__ mask,
          const int* __restrict__ children)
{
    extern __shared__ char sm[];
    float*  As = (float*)sm;
    float2* Bf = (float2*)(sm + AS_BYTES);

    const int tid = threadIdx.x, wid = tid >> 5, lane = tid & 31;
    const int wr = wid & 3, wc = wid >> 2;
    const int row0 = blockIdx.x * 128, e = s + n;

    // stage A = summed child rows
    for (int i = tid; i < 4096; i += 256) {
        int row = i >> 5, f4 = i & 31;
        int node = s + row0 + row;
        bool v = node < e;
        int nb = v ? node : s;
        float4 acc4 = make_float4(0.f, 0.f, 0.f, 0.f);
        if (LEAF) {
#pragma unroll
            for (int c = 0; c < 8; c++) {
                int cc = children[(size_t)nb * 8 + c];
                int mm = mask[cc];
                float fm = v ? (float)mm : 0.f;
                float4 t = ((const float4*)g_T)[(size_t)(x[cc] * mm) * 32 + f4];
                acc4.x = fmaf(t.x, fm, acc4.x); acc4.y = fmaf(t.y, fm, acc4.y);
                acc4.z = fmaf(t.z, fm, acc4.z); acc4.w = fmaf(t.w, fm, acc4.w);
            }
        } else {
            const float4* base = (const float4*)(g_h + (size_t)(nb * 8 + 1) * 128);
#pragma unroll
            for (int c = 0; c < 8; c++) {
                float4 t = base[c * 32 + f4];
                acc4.x += t.x; acc4.y += t.y; acc4.z += t.z; acc4.w += t.w;
            }
            if (!v) acc4 = make_float4(0.f, 0.f, 0.f, 0.f);
        }
        *(float4*)&As[row * 132 + f4 * 4] = acc4;
    }
    load_Bf(Bf, 1, tid); // U
    __syncthreads();

    float acc[2][8][4];
#pragma unroll
    for (int a = 0; a < 2; a++)
#pragma unroll
        for (int b = 0; b < 8; b++)
#pragma unroll
            for (int c = 0; c < 4; c++) acc[a][b][c] = 0.f;
    gemm_core(As, Bf, wr, wc, lane, acc);

#pragma unroll
    for (int mt = 0; mt < 2; mt++)
#pragma unroll
        for (int h = 0; h < 2; h++) {
            const int node = s + row0 + wr * 32 + mt * 16 + (lane >> 2) + h * 8;
            if (node < e) {
                const float mf = (float)mask[node];
                const size_t xm = (size_t)(x[node] * mask[node]);
#pragma unroll
                for (int nt = 0; nt < 8; nt++) {
                    const int col = wc * 64 + nt * 8 + (lane & 3) * 2;
                    float2 p = *(const float2*)&g_Pb[xm * 128 + col];
                    float o0 = tanhf(acc[mt][nt][h * 2]     + p.x * mf);
                    float o1 = tanhf(acc[mt][nt][h * 2 + 1] + p.y * mf);
                    *(float2*)&g_h[(size_t)node * 128 + col] = make_float2(o0, o1);
                }
            }
        }
}

// ---------------------------------------------------------------------------
// k_node: per-node kernel for tiny levels (block per node, 128 threads)
// ---------------------------------------------------------------------------
__global__ void __launch_bounds__(128, 8)
k_node(int s, const int* __restrict__ x, const int* __restrict__ mask,
       const int* __restrict__ children, const float* __restrict__ U)
{
    __shared__ float agg[128];
    const int node = s + blockIdx.x;
    const int t = threadIdx.x;

    float sum = 0.f;
#pragma unroll
    for (int c = 0; c < 8; c++)
        sum += g_h[(size_t)children[(size_t)node * 8 + c] * 128 + t];
    agg[t] = sum;
    __syncthreads();

    float a0 = 0.f, a1 = 0.f, a2 = 0.f, a3 = 0.f;
#pragma unroll 8
    for (int k = 0; k < 128; k += 4) {
        a0 = fmaf(agg[k + 0], U[(k + 0) * 128 + t], a0);
        a1 = fmaf(agg[k + 1], U[(k + 1) * 128 + t], a1);
        a2 = fmaf(agg[k + 2], U[(k + 2) * 128 + t], a2);
        a3 = fmaf(agg[k + 3], U[(k + 3) * 128 + t], a3);
    }

    const float mf = (float)mask[node];
    const int xm = x[node] * mask[node];
    const float hin = g_Pb[(size_t)xm * 128 + t] * mf;
    g_h[(size_t)node * 128 + t] = tanhf(hin + (a0 + a1) + (a2 + a3));
}

// ---------------------------------------------------------------------------
// k_out_t: out[0..NINT) = g_h @ W_out + b_out
// ---------------------------------------------------------------------------
__global__ void __launch_bounds__(256, 1)
k_out_t(const float* __restrict__ b_out, float* __restrict__ out)
{
    extern __shared__ char sm[];
    float*  As = (float*)sm;
    float2* Bf = (float2*)(sm + AS_BYTES);

    const int tid = threadIdx.x, wid = tid >> 5, lane = tid & 31;
    const int wr = wid & 3, wc = wid >> 2;
    const int row0 = blockIdx.x * 128;

    for (int i = tid; i < 4096; i += 256) {
        int row = i >> 5, q = i & 31;
        int rr = row0 + row; if (rr >= NINT) rr = NINT - 1;
        float4 v = ((const float4*)g_h)[(size_t)rr * 32 + q];
        *(float4*)&As[row * 132 + q * 4] = v;
    }
    load_Bf(Bf, 2, tid); // W_out
    __syncthreads();

    float acc[2][8][4];
#pragma unroll
    for (int a = 0; a < 2; a++)
#pragma unroll
        for (int b = 0; b < 8; b++)
#pragma unroll
            for (int c = 0; c < 4; c++) acc[a][b][c] = 0.f;
    gemm_core(As, Bf, wr, wc, lane, acc);

#pragma unroll
    for (int mt = 0; mt < 2; mt++)
#pragma unroll
        for (int h = 0; h < 2; h++) {
            const int node = row0 + wr * 32 + mt * 16 + (lane >> 2) + h * 8;
            if (node < NINT) {
#pragma unroll
                for (int nt = 0; nt < 8; nt++) {
                    const int col = wc * 64 + nt * 8 + (lane & 3) * 2;
                    float2 b = *(const float2*)&b_out[col];
                    *(float2*)&out[(size_t)node * 128 + col] =
                        make_float2(acc[mt][nt][h * 2] + b.x,
                                    acc[mt][nt][h * 2 + 1] + b.y);
                }
            }
        }
}

// ---------------------------------------------------------------------------
// Leaf output gather: out[leaf] = mask * Q[x] + b_out
// ---------------------------------------------------------------------------
__global__ void __launch_bounds__(256)
k_out_leaf(const int* __restrict__ x, const int* __restrict__ mask,
           const float* __restrict__ b_out, float* __restrict__ out)
{
    const int idx = blockIdx.x * 256 + threadIdx.x;
    const int rr = idx >> 5;
    const int c = idx & 31;
    const int node = NINT + rr;
    const int m = mask[node];
    const int xm = x[node] * m;
    const float mf = (float)m;
    float4 q = ((const float4*)g_Q)[(size_t)xm * 32 + c];
    float4 b = ((const float4*)b_out)[c];
    float4 o = make_float4(fmaf(q.x, mf, b.x), fmaf(q.y, mf, b.y),
                           fmaf(q.z, mf, b.z), fmaf(q.w, mf, b.w));
    ((float4*)out)[(size_t)node * 32 + c] = o;
}

// ---------------------------------------------------------------------------
extern "C" void kernel_launch(void* const* d_in, const int* in_sizes, int n_in,
                              void* d_out, int out_size)
{
    const int*   x        = (const int*)  d_in[0];
    const int*   mask     = (const int*)  d_in[1];
    const int*   children = (const int*)  d_in[2];
    const float* emb      = (const float*)d_in[3];
    const float* W_in     = (const float*)d_in[4];
    const float* b_in     = (const float*)d_in[5];
    const float* U        = (const float*)d_in[6];
    const float* W_out    = (const float*)d_in[7];
    const float* b_out    = (const float*)d_in[8];
    float*       out      = (float*)d_out;
    (void)in_sizes; (void)n_in; (void)out_size;

    cudaFuncSetAttribute(k_vocab,          cudaFuncAttributeMaxDynamicSharedMemorySize, SMEM_BYTES);
    cudaFuncSetAttribute(k_level_t<true>,  cudaFuncAttributeMaxDynamicSharedMemorySize, SMEM_BYTES);
    cudaFuncSetAttribute(k_level_t<false>, cudaFuncAttributeMaxDynamicSharedMemorySize, SMEM_BYTES);
    cudaFuncSetAttribute(k_out_t,          cudaFuncAttributeMaxDynamicSharedMemorySize, SMEM_BYTES);

    k_prep<<<96, 256>>>(W_in, U, W_out);
    k_vocab<<<250, 256, SMEM_BYTES>>>(emb, b_in);

    k_level_t<true ><<<256, 256, SMEM_BYTES>>>(4681, 32768, x, mask, children); // L5
    k_level_t<false><<< 32, 256, SMEM_BYTES>>>( 585,  4096, x, mask, children); // L4
    k_node<<<512, 128>>>(73, x, mask, children, U);  // L3
    k_node<<< 64, 128>>>( 9, x, mask, children, U);  // L2
    k_node<<<  8, 128>>>( 1, x, mask, children, U);  // L1
    k_node<<<  1, 128>>>( 0, x, mask, children, U);  // L0

    k_out_t<<<(NINT + 127) / 128, 256, SMEM_BYTES>>>(b_out, out);
    k_out_leaf<<<32768, 256>>>(x, mask, b_out, out);
}